// round 14
// baseline (speedup 1.0000x reference)
#include <cuda_runtime.h>
#include <math.h>

// mParametricLIF: x [N=128, T=64, D=4096] f32 -> spikes [N,T,D] f32.
//   m = lam*m + k*(x - v);  v += m;  s = (v >= th);  v = s ? 0 : v;  out = s
// k = sigmoid(tau_param[0]), lam = lamb[0], th = th[0].
//
// R14 = R13 resubmit (R13 died to the transient broker "container failed
// twice" error; same class as R4/R6-7, both passed on identical resubmit).
// R12 burst pipeline resized for ONE co-resident wave:
//  - BT=64, S=8, double buffer = 16KB smem/block -> 14 blocks/SM
//  - grid = 2048 blocks; 148*14 = 2072 >= 2048 -> zero tail wave
//  - __launch_bounds__(64,14) caps regs at 73 (R12 used 72: safe)
//  - segregated 8-deep load/store bursts, cp.async.cg (L1 bypass),
//    per-thread wait_group (no barriers), __stcs stores.

#define S  8      // timesteps per burst / per buffer
#define BT 64     // threads per block (2 warps)

#define CP_ASYNC16(saddr, gptr)                                             \
    asm volatile("cp.async.cg.shared.global [%0], [%1], 16;\n"              \
                 :: "r"(saddr), "l"(gptr) : "memory")
#define CP_COMMIT()  asm volatile("cp.async.commit_group;\n" ::: "memory")
#define CP_WAIT(n)   asm volatile("cp.async.wait_group %0;\n" :: "n"(n) : "memory")

__device__ __forceinline__ void lif_step(float4 xv, float4& v, float4& m,
                                         float k, float lam, float th,
                                         float4& s)
{
    m.x = lam * m.x + k * (xv.x - v.x); v.x += m.x;
    m.y = lam * m.y + k * (xv.y - v.y); v.y += m.y;
    m.z = lam * m.z + k * (xv.z - v.z); v.z += m.z;
    m.w = lam * m.w + k * (xv.w - v.w); v.w += m.w;

    s.x = (v.x >= th) ? 1.0f : 0.0f;
    s.y = (v.y >= th) ? 1.0f : 0.0f;
    s.z = (v.z >= th) ? 1.0f : 0.0f;
    s.w = (v.w >= th) ? 1.0f : 0.0f;

    v.x = (s.x != 0.0f) ? 0.0f : v.x;
    v.y = (s.y != 0.0f) ? 0.0f : v.y;
    v.z = (s.z != 0.0f) ? 0.0f : v.z;
    v.w = (s.w != 0.0f) ? 0.0f : v.w;
}

__global__ __launch_bounds__(BT, 14) void mplif_kernel(
    const float4* __restrict__ x4,
    const float* __restrict__ tau_param,
    const float* __restrict__ lamb,
    const float* __restrict__ thr,
    float4* __restrict__ out4,
    int T, int DC /* D/4 */)
{
    __shared__ float4 stage[2][S][BT];   // 16 KB, stage-major, conflict-free

    int tid = blockIdx.x * BT + threadIdx.x;   // lanes = 2048*64 exactly
    int n = tid / DC;
    int c = tid - n * DC;
    long base = (long)n * T * DC + c;

    const float k   = 1.0f / (1.0f + expf(-tau_param[0]));
    const float lam = lamb[0];
    const float th  = thr[0];

    const float4* __restrict__ px = x4 + base;    // prefetch cursor
    float4*       __restrict__ po = out4 + base;  // store cursor

    unsigned int s_tid = (unsigned int)__cvta_generic_to_shared(
                             &stage[0][0][threadIdx.x]);
    const unsigned int slot = BT * sizeof(float4);        // 1024 B per stage
    const unsigned int bufB = S * slot;                   // buffer stride

    float4 v = make_float4(0.f, 0.f, 0.f, 0.f);
    float4 m = make_float4(0.f, 0.f, 0.f, 0.f);

    // Prologue: two full load bursts (groups G0 -> buf0, G1 -> buf1).
    #pragma unroll
    for (int j = 0; j < S; j++) { CP_ASYNC16(s_tid + j * slot, px); px += DC; }
    CP_COMMIT();
    #pragma unroll
    for (int j = 0; j < S; j++) { CP_ASYNC16(s_tid + bufB + j * slot, px); px += DC; }
    CP_COMMIT();

    int cur = 0;
    // Steady state: consume one buffer per iteration, refill it.
    for (int t0 = 0; t0 < T - 2 * S; t0 += S) {
        CP_WAIT(1);                               // buffer `cur` ready
        // Compute + STORE BURST (8 STG.128 back-to-back).
        #pragma unroll
        for (int j = 0; j < S; j++) {
            float4 s;
            lif_step(stage[cur][j][threadIdx.x], v, m, k, lam, th, s);
            __stcs(po, s);
            po += DC;
        }
        // LOAD BURST refilling the buffer just consumed.
        unsigned int b = s_tid + (unsigned int)cur * bufB;
        #pragma unroll
        for (int j = 0; j < S; j++) { CP_ASYNC16(b + j * slot, px); px += DC; }
        CP_COMMIT();
        cur ^= 1;
    }

    // Drain: second-to-last buffer.
    CP_WAIT(1);
    #pragma unroll
    for (int j = 0; j < S; j++) {
        float4 s;
        lif_step(stage[cur][j][threadIdx.x], v, m, k, lam, th, s);
        __stcs(po, s);
        po += DC;
    }
    cur ^= 1;

    // Drain: last buffer.
    CP_WAIT(0);
    #pragma unroll
    for (int j = 0; j < S; j++) {
        float4 s;
        lif_step(stage[cur][j][threadIdx.x], v, m, k, lam, th, s);
        __stcs(po, s);
        po += DC;
    }
}

extern "C" void kernel_launch(void* const* d_in, const int* in_sizes, int n_in,
                              void* d_out, int out_size)
{
    const float* x         = (const float*)d_in[0];
    const float* tau_param = (const float*)d_in[1];
    const float* lamb      = (const float*)d_in[2];
    const float* th        = (const float*)d_in[3];
    float* out             = (float*)d_out;

    const int N = 128, T = 64, D = 4096;
    const int DC = D / 4;
    const int lanes = N * DC;   // 131072 float4 lanes

    dim3 block(BT);
    dim3 grid(lanes / BT);      // 2048 blocks, exact
    mplif_kernel<<<grid, block>>>((const float4*)x, tau_param, lamb, th,
                                  (float4*)out, T, DC);
}

// round 15
// speedup vs baseline: 1.0013x; 1.0013x over previous
#include <cuda_runtime.h>
#include <math.h>

// mParametricLIF: x [N=128, T=64, D=4096] f32 -> spikes [N,T,D] f32.
//   m = lam*m + k*(x - v);  v += m;  s = (v >= th);  v = s ? 0 : v;  out = s
// k = sigmoid(tau_param[0]), lam = lamb[0], th = th[0].
//
// R15 = FINAL: exact resubmit of R12, the best measured kernel
// (39.7us kernel / 49.0us bench, DRAM 5.40TB/s).
// Fourteen rounds of evidence: all structurally sound variants (reg-resident
// bursts, interleaved cp.async, L2 evict_last pinning, one-wave geometry,
// occ 31-73%) converge to 5.2-5.4TB/s DRAM / ~6.7TB/s application
// throughput. Traffic is irreducible (read x once, write spikes once, f32 by
// contract) => this is the achieved-DRAM ceiling for a 1:1 R/W mixed stream.
//
// Structure: cp.async double-buffered BURST pipeline.
//  - reads and writes hit DRAM in segregated 8-deep bursts (turnaround-
//    friendly) AND >=8 loads/thread in flight at all times (no sawtooth).
//  - in-flight data lives in smem (2 x 8 x 128 x 16B = 32KB/block);
//    per-thread cp.async wait_group, zero block barriers.
//  - cp.async.cg bypasses L1; stores __stcs (write-once, evict-first).

#define S  8      // timesteps per burst / per buffer
#define BT 128    // threads per block

#define CP_ASYNC16(saddr, gptr)                                             \
    asm volatile("cp.async.cg.shared.global [%0], [%1], 16;\n"              \
                 :: "r"(saddr), "l"(gptr) : "memory")
#define CP_COMMIT()  asm volatile("cp.async.commit_group;\n" ::: "memory")
#define CP_WAIT(n)   asm volatile("cp.async.wait_group %0;\n" :: "n"(n) : "memory")

__device__ __forceinline__ void lif_step(float4 xv, float4& v, float4& m,
                                         float k, float lam, float th,
                                         float4& s)
{
    m.x = lam * m.x + k * (xv.x - v.x); v.x += m.x;
    m.y = lam * m.y + k * (xv.y - v.y); v.y += m.y;
    m.z = lam * m.z + k * (xv.z - v.z); v.z += m.z;
    m.w = lam * m.w + k * (xv.w - v.w); v.w += m.w;

    s.x = (v.x >= th) ? 1.0f : 0.0f;
    s.y = (v.y >= th) ? 1.0f : 0.0f;
    s.z = (v.z >= th) ? 1.0f : 0.0f;
    s.w = (v.w >= th) ? 1.0f : 0.0f;

    v.x = (s.x != 0.0f) ? 0.0f : v.x;
    v.y = (s.y != 0.0f) ? 0.0f : v.y;
    v.z = (s.z != 0.0f) ? 0.0f : v.z;
    v.w = (s.w != 0.0f) ? 0.0f : v.w;
}

__global__ __launch_bounds__(BT) void mplif_kernel(
    const float4* __restrict__ x4,
    const float* __restrict__ tau_param,
    const float* __restrict__ lamb,
    const float* __restrict__ thr,
    float4* __restrict__ out4,
    int T, int DC /* D/4 */)
{
    __shared__ float4 stage[2][S][BT];   // 32 KB, stage-major, conflict-free

    int tid = blockIdx.x * BT + threadIdx.x;   // lanes = 1024*128 exactly
    int n = tid / DC;
    int c = tid - n * DC;
    long base = (long)n * T * DC + c;

    const float k   = 1.0f / (1.0f + expf(-tau_param[0]));
    const float lam = lamb[0];
    const float th  = thr[0];

    const float4* __restrict__ px = x4 + base;    // prefetch cursor
    float4*       __restrict__ po = out4 + base;  // store cursor

    unsigned int s_tid = (unsigned int)__cvta_generic_to_shared(
                             &stage[0][0][threadIdx.x]);
    const unsigned int slot = BT * sizeof(float4);        // 2048 B per stage
    const unsigned int bufB = S * slot;                   // buffer stride

    float4 v = make_float4(0.f, 0.f, 0.f, 0.f);
    float4 m = make_float4(0.f, 0.f, 0.f, 0.f);

    // Prologue: two full load bursts (groups G0 -> buf0, G1 -> buf1).
    #pragma unroll
    for (int j = 0; j < S; j++) { CP_ASYNC16(s_tid + j * slot, px); px += DC; }
    CP_COMMIT();
    #pragma unroll
    for (int j = 0; j < S; j++) { CP_ASYNC16(s_tid + bufB + j * slot, px); px += DC; }
    CP_COMMIT();

    int cur = 0;
    // Steady state: consume one buffer per iteration, refill it.
    for (int t0 = 0; t0 < T - 2 * S; t0 += S) {
        CP_WAIT(1);                               // buffer `cur` ready
        // Compute + STORE BURST (8 STG.128 back-to-back).
        #pragma unroll
        for (int j = 0; j < S; j++) {
            float4 s;
            lif_step(stage[cur][j][threadIdx.x], v, m, k, lam, th, s);
            __stcs(po, s);
            po += DC;
        }
        // LOAD BURST refilling the buffer just consumed.
        unsigned int b = s_tid + (unsigned int)cur * bufB;
        #pragma unroll
        for (int j = 0; j < S; j++) { CP_ASYNC16(b + j * slot, px); px += DC; }
        CP_COMMIT();
        cur ^= 1;
    }

    // Drain: second-to-last buffer.
    CP_WAIT(1);
    #pragma unroll
    for (int j = 0; j < S; j++) {
        float4 s;
        lif_step(stage[cur][j][threadIdx.x], v, m, k, lam, th, s);
        __stcs(po, s);
        po += DC;
    }
    cur ^= 1;

    // Drain: last buffer.
    CP_WAIT(0);
    #pragma unroll
    for (int j = 0; j < S; j++) {
        float4 s;
        lif_step(stage[cur][j][threadIdx.x], v, m, k, lam, th, s);
        __stcs(po, s);
        po += DC;
    }
}

extern "C" void kernel_launch(void* const* d_in, const int* in_sizes, int n_in,
                              void* d_out, int out_size)
{
    const float* x         = (const float*)d_in[0];
    const float* tau_param = (const float*)d_in[1];
    const float* lamb      = (const float*)d_in[2];
    const float* th        = (const float*)d_in[3];
    float* out             = (float*)d_out;

    const int N = 128, T = 64, D = 4096;
    const int DC = D / 4;
    const int lanes = N * DC;

    dim3 block(BT);
    dim3 grid(lanes / BT);   // 1024 blocks, exact
    mplif_kernel<<<grid, block>>>((const float4*)x, tau_param, lamb, th,
                                  (float4*)out, T, DC);
}

// round 16
// speedup vs baseline: 1.0033x; 1.0020x over previous
#include <cuda_runtime.h>
#include <math.h>

// mParametricLIF: x [N=128, T=64, D=4096] f32 -> spikes [N,T,D] f32.
//   m = lam*m + k*(x - v);  v += m;  s = (v >= th);  v = s ? 0 : v;  out = s
// k = sigmoid(tau_param[0]), lam = lamb[0], th = th[0].
//
// R16 = FINAL (frozen): exact R12/R15, best measured (38.8us kernel /
// 49.0us bench, DRAM 5.53TB/s).
// Why frozen: application throughput = 268MB / 38.8us = 6.9TB/s, which
// matches the measured LTS chip cap (~6300 B/cyc, path-independent).
// The kernel is at the L2/LTS crossbar ceiling, not a DRAM or scheduling
// limit; traffic is contractually irreducible (read x once, write spikes
// once, both f32). 15 rounds of variants (reg bursts, interleaved cp.async,
// evict_last pinning, one-wave geometry, occ 30-73%) all converge here.
//
// Structure: cp.async double-buffered BURST pipeline.
//  - reads and writes hit DRAM in segregated 8-deep bursts (turnaround-
//    friendly) AND >=8 loads/thread in flight at all times (no sawtooth).
//  - in-flight data lives in smem (2 x 8 x 128 x 16B = 32KB/block);
//    per-thread cp.async wait_group, zero block barriers.
//  - cp.async.cg bypasses L1; stores __stcs (write-once, evict-first).

#define S  8      // timesteps per burst / per buffer
#define BT 128    // threads per block

#define CP_ASYNC16(saddr, gptr)                                             \
    asm volatile("cp.async.cg.shared.global [%0], [%1], 16;\n"              \
                 :: "r"(saddr), "l"(gptr) : "memory")
#define CP_COMMIT()  asm volatile("cp.async.commit_group;\n" ::: "memory")
#define CP_WAIT(n)   asm volatile("cp.async.wait_group %0;\n" :: "n"(n) : "memory")

__device__ __forceinline__ void lif_step(float4 xv, float4& v, float4& m,
                                         float k, float lam, float th,
                                         float4& s)
{
    m.x = lam * m.x + k * (xv.x - v.x); v.x += m.x;
    m.y = lam * m.y + k * (xv.y - v.y); v.y += m.y;
    m.z = lam * m.z + k * (xv.z - v.z); v.z += m.z;
    m.w = lam * m.w + k * (xv.w - v.w); v.w += m.w;

    s.x = (v.x >= th) ? 1.0f : 0.0f;
    s.y = (v.y >= th) ? 1.0f : 0.0f;
    s.z = (v.z >= th) ? 1.0f : 0.0f;
    s.w = (v.w >= th) ? 1.0f : 0.0f;

    v.x = (s.x != 0.0f) ? 0.0f : v.x;
    v.y = (s.y != 0.0f) ? 0.0f : v.y;
    v.z = (s.z != 0.0f) ? 0.0f : v.z;
    v.w = (s.w != 0.0f) ? 0.0f : v.w;
}

__global__ __launch_bounds__(BT) void mplif_kernel(
    const float4* __restrict__ x4,
    const float* __restrict__ tau_param,
    const float* __restrict__ lamb,
    const float* __restrict__ thr,
    float4* __restrict__ out4,
    int T, int DC /* D/4 */)
{
    __shared__ float4 stage[2][S][BT];   // 32 KB, stage-major, conflict-free

    int tid = blockIdx.x * BT + threadIdx.x;   // lanes = 1024*128 exactly
    int n = tid / DC;
    int c = tid - n * DC;
    long base = (long)n * T * DC + c;

    const float k   = 1.0f / (1.0f + expf(-tau_param[0]));
    const float lam = lamb[0];
    const float th  = thr[0];

    const float4* __restrict__ px = x4 + base;    // prefetch cursor
    float4*       __restrict__ po = out4 + base;  // store cursor

    unsigned int s_tid = (unsigned int)__cvta_generic_to_shared(
                             &stage[0][0][threadIdx.x]);
    const unsigned int slot = BT * sizeof(float4);        // 2048 B per stage
    const unsigned int bufB = S * slot;                   // buffer stride

    float4 v = make_float4(0.f, 0.f, 0.f, 0.f);
    float4 m = make_float4(0.f, 0.f, 0.f, 0.f);

    // Prologue: two full load bursts (groups G0 -> buf0, G1 -> buf1).
    #pragma unroll
    for (int j = 0; j < S; j++) { CP_ASYNC16(s_tid + j * slot, px); px += DC; }
    CP_COMMIT();
    #pragma unroll
    for (int j = 0; j < S; j++) { CP_ASYNC16(s_tid + bufB + j * slot, px); px += DC; }
    CP_COMMIT();

    int cur = 0;
    // Steady state: consume one buffer per iteration, refill it.
    for (int t0 = 0; t0 < T - 2 * S; t0 += S) {
        CP_WAIT(1);                               // buffer `cur` ready
        // Compute + STORE BURST (8 STG.128 back-to-back).
        #pragma unroll
        for (int j = 0; j < S; j++) {
            float4 s;
            lif_step(stage[cur][j][threadIdx.x], v, m, k, lam, th, s);
            __stcs(po, s);
            po += DC;
        }
        // LOAD BURST refilling the buffer just consumed.
        unsigned int b = s_tid + (unsigned int)cur * bufB;
        #pragma unroll
        for (int j = 0; j < S; j++) { CP_ASYNC16(b + j * slot, px); px += DC; }
        CP_COMMIT();
        cur ^= 1;
    }

    // Drain: second-to-last buffer.
    CP_WAIT(1);
    #pragma unroll
    for (int j = 0; j < S; j++) {
        float4 s;
        lif_step(stage[cur][j][threadIdx.x], v, m, k, lam, th, s);
        __stcs(po, s);
        po += DC;
    }
    cur ^= 1;

    // Drain: last buffer.
    CP_WAIT(0);
    #pragma unroll
    for (int j = 0; j < S; j++) {
        float4 s;
        lif_step(stage[cur][j][threadIdx.x], v, m, k, lam, th, s);
        __stcs(po, s);
        po += DC;
    }
}

extern "C" void kernel_launch(void* const* d_in, const int* in_sizes, int n_in,
                              void* d_out, int out_size)
{
    const float* x         = (const float*)d_in[0];
    const float* tau_param = (const float*)d_in[1];
    const float* lamb      = (const float*)d_in[2];
    const float* th        = (const float*)d_in[3];
    float* out             = (float*)d_out;

    const int N = 128, T = 64, D = 4096;
    const int DC = D / 4;
    const int lanes = N * DC;

    dim3 block(BT);
    dim3 grid(lanes / BT);   // 1024 blocks, exact
    mplif_kernel<<<grid, block>>>((const float4*)x, tau_param, lamb, th,
                                  (float4*)out, T, DC);
}